// round 2
// baseline (speedup 1.0000x reference)
#include <cuda_runtime.h>
#include <cuda_bf16.h>

// Problem constants
#define NB   16
#define NCIN 64
#define H1   128
#define H2   256
#define Q1   64
#define Q2   16

// Tiling
#define TH   64
#define TW   32
#define CC   4
#define SP   35     // smem row stride in floats: odd => conflict-free (see analysis)

typedef unsigned long long ull;

// Scratch (allocation-free rule: __device__ globals)
__device__ float  g_up[(size_t)NB * NCIN * H2 * H2];          // 256 MB intermediate
__device__ float4 g_wpre [Q1 * NCIN * 9];
__device__ float4 g_wpost[Q2 * NCIN * 9];

// ---------------- packed f32x2 helpers (Blackwell FFMA2) ----------------
__device__ __forceinline__ ull ffma2(ull a, ull b, ull c) {
    ull d;
    asm("fma.rn.f32x2 %0, %1, %2, %3;" : "=l"(d) : "l"(a), "l"(b), "l"(c));
    return d;
}
__device__ __forceinline__ ull pack2(float x) {
    ull d; asm("mov.b64 %0, {%1, %1};" : "=l"(d) : "f"(x)); return d;
}
__device__ __forceinline__ ull pack2f(float x, float y) {
    ull d; asm("mov.b64 %0, {%1, %2};" : "=l"(d) : "f"(x), "f"(y)); return d;
}
__device__ __forceinline__ float2 unpack2(ull v) {
    float2 r; asm("mov.b64 {%0, %1}, %2;" : "=f"(r.x), "=f"(r.y) : "l"(v)); return r;
}

// ---------------- weight reorder ----------------
__global__ void reorder_pre(const float* __restrict__ w) {
    int i = blockIdx.x * blockDim.x + threadIdx.x;
    if (i >= Q1 * NCIN * 9) return;
    int k = i % 9, cin = (i / 9) % NCIN, q = i / (9 * NCIN);
    float4 v;
    v.x = w[(((q      ) * NCIN + cin) * 9) + k];
    v.y = w[(((q +  64) * NCIN + cin) * 9) + k];
    v.z = w[(((q + 128) * NCIN + cin) * 9) + k];
    v.w = w[(((q + 192) * NCIN + cin) * 9) + k];
    g_wpre[i] = v;
}
__global__ void reorder_post(const float* __restrict__ w) {
    int i = blockIdx.x * blockDim.x + threadIdx.x;
    if (i >= Q2 * NCIN * 9) return;
    int k = i % 9, cin = (i / 9) % NCIN, q = i / (9 * NCIN);
    float4 v;
    v.x = w[(((4*q + 0) * NCIN + cin) * 9) + k];
    v.y = w[(((4*q + 1) * NCIN + cin) * 9) + k];
    v.z = w[(((4*q + 2) * NCIN + cin) * 9) + k];
    v.w = w[(((4*q + 3) * NCIN + cin) * 9) + k];
    g_wpost[i] = v;
}

// ---------------------------------------------------------------------------
// Tiled 3x3 conv with FFMA2. Block: (b, quad), 64x32 tile, 256 threads.
// Thread: 1 out row x 8 cols x 4 channels = 16 packed fp32x2 accumulators.
// ---------------------------------------------------------------------------
template<int HIN, int Q, bool WAVELET>
__global__ __launch_bounds__(256, 2)
void conv3x3_q(const float* __restrict__ xp,
               const float* __restrict__ bias,
               float* __restrict__ outp)
{
    constexpr int WIN = HIN;
    __shared__ float  sIn[CC][TH + 2][SP];
    __shared__ float4 sW[NCIN * 9];

    const int tid = threadIdx.x;
    const int wt  = blockIdx.x;
    const int ht  = blockIdx.y;
    const int z   = blockIdx.z;
    const int b   = z / Q;
    const int q   = z % Q;
    const int h0  = ht * TH;
    const int w0b = wt * TW;

    const float4* wg = (WAVELET ? g_wpre : g_wpost) + q * NCIN * 9;
    for (int i = tid; i < NCIN * 9; i += 256) sW[i] = wg[i];

    const int ro  = tid >> 2;      // out row 0..63
    const int seg = tid & 3;       // col segment: cols 8*seg .. 8*seg+7
    const int c0  = seg * 8;

    ull acc01[8], acc23[8];
    {
        float b0, b1, b2, b3;
        if (WAVELET) { b0 = bias[q]; b1 = bias[q+64]; b2 = bias[q+128]; b3 = bias[q+192]; }
        else         { b0 = bias[4*q]; b1 = bias[4*q+1]; b2 = bias[4*q+2]; b3 = bias[4*q+3]; }
        ull i01 = pack2f(b0, b1), i23 = pack2f(b2, b3);
        #pragma unroll
        for (int p = 0; p < 8; ++p) { acc01[p] = i01; acc23[p] = i23; }
    }

    const float* x  = WAVELET ? xp : g_up;
    const float* xb = x + (size_t)b * NCIN * HIN * WIN;

    const int lr = tid >> 5;       // warp id 0..7 : loader row group
    const int lc = tid & 31;       // loader col

    for (int cc = 0; cc < NCIN / CC; ++cc) {
        __syncthreads();
        // ---- cooperative load: warp per row, lane per col (coalesced) ----
        #pragma unroll
        for (int ci = 0; ci < CC; ++ci) {
            const float* src = xb + (size_t)(cc * CC + ci) * HIN * WIN;
            for (int r = lr; r < TH + 2; r += 8) {
                int gh = h0 - 1 + r;
                bool hok = (gh >= 0) && (gh < HIN);
                for (int c = lc; c < TW + 2; c += 32) {
                    int gw = w0b - 1 + c;
                    float v = 0.0f;
                    if (hok && gw >= 0 && gw < WIN)
                        v = __ldg(&src[(size_t)gh * WIN + gw]);
                    sIn[ci][r][c] = v;
                }
            }
        }
        __syncthreads();

        // ---- compute: FFMA2 mainloop ----
        #pragma unroll
        for (int ci = 0; ci < CC; ++ci) {
            const float4* wrow = &sW[(cc * CC + ci) * 9];
            #pragma unroll
            for (int jj = 0; jj < 3; ++jj) {      // input row ro+jj (padded)
                ull xp2[10];
                #pragma unroll
                for (int u = 0; u < 10; ++u)
                    xp2[u] = pack2(sIn[ci][ro + jj][c0 + u]);
                #pragma unroll
                for (int kw = 0; kw < 3; ++kw) {
                    float4 wv = wrow[jj * 3 + kw];
                    ull w01 = pack2f(wv.x, wv.y);
                    ull w23 = pack2f(wv.z, wv.w);
                    #pragma unroll
                    for (int p = 0; p < 8; ++p) {
                        acc01[p] = ffma2(xp2[p + kw], w01, acc01[p]);
                        acc23[p] = ffma2(xp2[p + kw], w23, acc23[p]);
                    }
                }
            }
        }
    }

    // ------------------------- epilogue -------------------------
    const int gh   = h0  + ro;
    const int ocol = w0b + c0;

    if (WAVELET) {
        float* up = g_up + (size_t)(b * NCIN + q) * (2 * HIN) * (2 * WIN);
        const size_t base0 = (size_t)(2 * gh) * (2 * WIN);
        const size_t base1 = base0 + (2 * WIN);
        #pragma unroll
        for (int p = 0; p < 8; p += 2) {
            float2 v01a = unpack2(acc01[p]);      // ll, lh
            float2 v23a = unpack2(acc23[p]);      // hl, hh
            float2 v01b = unpack2(acc01[p + 1]);
            float2 v23b = unpack2(acc23[p + 1]);
            float ee0 = 0.5f * (v01a.x + v01a.y + v23a.x + v23a.y);
            float eo0 = 0.5f * (v01a.x - v01a.y + v23a.x - v23a.y);
            float oe0 = 0.5f * (v01a.x + v01a.y - v23a.x - v23a.y);
            float oo0 = 0.5f * (v01a.x - v01a.y - v23a.x + v23a.y);
            float ee1 = 0.5f * (v01b.x + v01b.y + v23b.x + v23b.y);
            float eo1 = 0.5f * (v01b.x - v01b.y + v23b.x - v23b.y);
            float oe1 = 0.5f * (v01b.x + v01b.y - v23b.x - v23b.y);
            float oo1 = 0.5f * (v01b.x - v01b.y - v23b.x + v23b.y);
            int gw2 = 2 * (ocol + p);
            *(float4*)&up[base0 + gw2] = make_float4(ee0, eo0, ee1, eo1);
            *(float4*)&up[base1 + gw2] = make_float4(oe0, oo0, oe1, oo1);
        }
    } else {
        #pragma unroll
        for (int c = 0; c < 4; ++c) {
            float v[8];
            #pragma unroll
            for (int p = 0; p < 8; ++p) {
                float2 t = (c < 2) ? unpack2(acc01[p]) : unpack2(acc23[p]);
                v[p] = (c & 1) ? t.y : t.x;
            }
            float* dst = outp + (size_t)(b * (4 * Q) + 4 * q + c) * HIN * WIN
                              + (size_t)gh * WIN + ocol;
            *(float4*)&dst[0] = make_float4(v[0], v[1], v[2], v[3]);
            *(float4*)&dst[4] = make_float4(v[4], v[5], v[6], v[7]);
        }
    }
}

extern "C" void kernel_launch(void* const* d_in, const int* in_sizes, int n_in,
                              void* d_out, int out_size)
{
    (void)in_sizes; (void)n_in; (void)out_size;
    const float* x      = (const float*)d_in[0];
    const float* w_pre  = (const float*)d_in[1];
    const float* b_pre  = (const float*)d_in[2];
    const float* w_post = (const float*)d_in[3];
    const float* b_post = (const float*)d_in[4];
    float* out = (float*)d_out;

    reorder_pre <<<(Q1 * NCIN * 9 + 255) / 256, 256>>>(w_pre);
    reorder_post<<<(Q2 * NCIN * 9 + 255) / 256, 256>>>(w_post);

    {   // conv_pre + wavelet upsample -> g_up
        dim3 grid(H1 / TW, H1 / TH, NB * Q1);   // (4, 2, 1024)
        conv3x3_q<H1, Q1, true><<<grid, 256>>>(x, b_pre, nullptr);
    }
    {   // conv_post: g_up -> out
        dim3 grid(H2 / TW, H2 / TH, NB * Q2);   // (8, 4, 256)
        conv3x3_q<H2, Q2, false><<<grid, 256>>>(nullptr, b_post, out);
    }
}